// round 6
// baseline (speedup 1.0000x reference)
#include <cuda_runtime.h>
#include <cstdint>

// Anisotropic RBF kernel matrix on GB300 via legacy-path split-tf32 MMA
// (mma.sync m16n8k8 + ldmatrix; tcgen05 is ptxas-gated off under this bench):
//   out[n][m] = exp2( x[n] . (2*log2e*gamma*y[m]) - sqx'[n] - sqy'[m] )
// fp32 emulated by tf32 3-pass: Ah*Bh + Ah*Bl + Al*Bh.

#define NROWS 8192
#define MROWS 8192
#define DDIM  64
#define TILE_M 128
#define TILE_N 64
#define L2E 1.4426950408889634f

__device__ float g_sqx[NROWS];
__device__ float g_sqy[MROWS];

// ---------------- helpers ----------------
__device__ __forceinline__ uint32_t smem_u32(const void* p) {
    uint32_t a;
    asm("{ .reg .u64 t; cvta.to.shared.u64 t, %1; cvt.u32.u64 %0, t; }"
        : "=r"(a) : "l"(p));
    return a;
}
__device__ __forceinline__ uint32_t tf32of(float f) {
    uint32_t r;
    asm("cvt.rna.tf32.f32 %0, %1;" : "=r"(r) : "f"(f));
    return r;
}
__device__ __forceinline__ float ex2f(float x) {
    float r;
    asm("ex2.approx.f32 %0, %1;" : "=f"(r) : "f"(x));
    return r;
}
__device__ __forceinline__ void ldsm_x4(uint32_t addr, uint32_t r[4]) {
    asm volatile("ldmatrix.sync.aligned.m8n8.x4.shared.b16 {%0,%1,%2,%3}, [%4];"
                 : "=r"(r[0]), "=r"(r[1]), "=r"(r[2]), "=r"(r[3]) : "r"(addr));
}
__device__ __forceinline__ void mma_tf32(float d[4], const uint32_t a[4],
                                         uint32_t b0, uint32_t b1) {
    asm volatile(
        "mma.sync.aligned.m16n8k8.row.col.f32.tf32.tf32.f32 "
        "{%0,%1,%2,%3}, {%4,%5,%6,%7}, {%8,%9}, {%0,%1,%2,%3};"
        : "+f"(d[0]), "+f"(d[1]), "+f"(d[2]), "+f"(d[3])
        : "r"(a[0]), "r"(a[1]), "r"(a[2]), "r"(a[3]), "r"(b0), "r"(b1));
}
// 16B-chunk XOR swizzle inside a 256B row (16 chunks of 16B)
__device__ __forceinline__ uint32_t swaddr(uint32_t base, int row, int chunk) {
    return base + (uint32_t)(row * 256) + (uint32_t)((chunk ^ (row & 7)) << 4);
}
__device__ __forceinline__ void split2(float v, uint32_t& h, uint32_t& l) {
    h = tf32of(v);
    l = tf32of(v - __uint_as_float(h));
}

// smem layout (bytes): XH[128][64f] XL YH[64][64f] YL
#define S_XH 0
#define S_XL 32768
#define S_YH 65536
#define S_YL 81920
#define SMEM_TOTAL 98304

// ---- precompute log2e-scaled gamma-weighted squared norms ----
__global__ void precompute_kernel(const float* __restrict__ x,
                                  const float* __restrict__ y,
                                  const float* __restrict__ gamma) {
    int w = (blockIdx.x * blockDim.x + threadIdx.x) >> 5;
    int lane = threadIdx.x & 31;
    const float* src;
    float* dst;
    int row;
    if (w < NROWS) { src = x; dst = g_sqx; row = w; }
    else           { src = y; dst = g_sqy; row = w - NROWS; }
    float g0 = gamma[lane], g1 = gamma[lane + 32];
    float v0 = src[(size_t)row * DDIM + lane];
    float v1 = src[(size_t)row * DDIM + lane + 32];
    float s = g0 * v0 * v0 + g1 * v1 * v1;
    #pragma unroll
    for (int o = 16; o > 0; o >>= 1) s += __shfl_xor_sync(0xffffffffu, s, o);
    if (lane == 0) dst[row] = L2E * s;
}

// ---- main kernel: 128x64 tile/CTA, 8 warps (4x2), warp tile 32x32 ----
__global__ __launch_bounds__(256, 2) void rbf_mma_kernel(
    const float* __restrict__ x, const float* __restrict__ y,
    const float* __restrict__ gamma, float* __restrict__ out)
{
    extern __shared__ char smem[];
    const uint32_t sb = smem_u32(smem);
    const int tid = threadIdx.x;
    const int wid = tid >> 5;
    const int lane = tid & 31;
    const int rowBase = blockIdx.y * TILE_M;
    const int colBase = blockIdx.x * TILE_N;

    // ---- cooperative load + tf32 split into swizzled smem ----
    {   // X: 128 rows x 16 chunks; each thread: half a row (8 chunks)
        const int row = tid >> 1;
        const int half = (tid & 1) * 8;
        const float4* gx = reinterpret_cast<const float4*>(
            x + (size_t)(rowBase + row) * DDIM);
        #pragma unroll
        for (int i = 0; i < 8; ++i) {
            const int c = half + i;
            float4 v = gx[c];
            uint4 h, l;
            split2(v.x, h.x, l.x); split2(v.y, h.y, l.y);
            split2(v.z, h.z, l.z); split2(v.w, h.w, l.w);
            asm volatile("st.shared.v4.b32 [%0], {%1,%2,%3,%4};"
                         :: "r"(swaddr(sb + S_XH, row, c)),
                            "r"(h.x), "r"(h.y), "r"(h.z), "r"(h.w) : "memory");
            asm volatile("st.shared.v4.b32 [%0], {%1,%2,%3,%4};"
                         :: "r"(swaddr(sb + S_XL, row, c)),
                            "r"(l.x), "r"(l.y), "r"(l.z), "r"(l.w) : "memory");
        }
    }
    {   // Y: 64 rows x 16 chunks, scaled by 2*log2e*gamma; each thread: 4 chunks
        const int row = tid >> 2;
        const int cq = (tid & 3) * 4;
        const float4* gy = reinterpret_cast<const float4*>(
            y + (size_t)(colBase + row) * DDIM);
        const float4* gg = reinterpret_cast<const float4*>(gamma);
        #pragma unroll
        for (int i = 0; i < 4; ++i) {
            const int c = cq + i;
            float4 v = gy[c];
            float4 g = gg[c];
            float b0 = 2.f * L2E * g.x * v.x;
            float b1 = 2.f * L2E * g.y * v.y;
            float b2 = 2.f * L2E * g.z * v.z;
            float b3 = 2.f * L2E * g.w * v.w;
            uint4 h, l;
            split2(b0, h.x, l.x); split2(b1, h.y, l.y);
            split2(b2, h.z, l.z); split2(b3, h.w, l.w);
            asm volatile("st.shared.v4.b32 [%0], {%1,%2,%3,%4};"
                         :: "r"(swaddr(sb + S_YH, row, c)),
                            "r"(h.x), "r"(h.y), "r"(h.z), "r"(h.w) : "memory");
            asm volatile("st.shared.v4.b32 [%0], {%1,%2,%3,%4};"
                         :: "r"(swaddr(sb + S_YL, row, c)),
                            "r"(l.x), "r"(l.y), "r"(l.z), "r"(l.w) : "memory");
        }
    }
    __syncthreads();

    // ---- mainloop ----
    const int warpM = wid >> 1;   // 0..3 -> rows 32*warpM
    const int warpN = wid & 1;    // 0..1 -> cols 32*warpN

    float acc[2][4][4];
    #pragma unroll
    for (int mt = 0; mt < 2; ++mt)
        #pragma unroll
        for (int nt = 0; nt < 4; ++nt)
            #pragma unroll
            for (int i = 0; i < 4; ++i) acc[mt][nt][i] = 0.f;

    const int mlane = lane & 15;             // A: row within m16 tile
    const int abit  = lane >> 4;             // A: chunk select
    const int bn    = (lane & 7) + ((lane >> 4) << 3);  // B: n within n16 group
    const int bbit  = (lane >> 3) & 1;       // B: chunk select

    #pragma unroll
    for (int ks = 0; ks < 8; ++ks) {
        uint32_t ah[2][4], al[2][4], bh[2][4], bl[2][4];
        #pragma unroll
        for (int mt = 0; mt < 2; ++mt) {
            const int r = warpM * 32 + mt * 16 + mlane;
            const int c = ks * 2 + abit;
            ldsm_x4(swaddr(sb + S_XH, r, c), ah[mt]);
            ldsm_x4(swaddr(sb + S_XL, r, c), al[mt]);
        }
        #pragma unroll
        for (int g = 0; g < 2; ++g) {
            const int n = warpN * 32 + g * 16 + bn;
            const int c = ks * 2 + bbit;
            ldsm_x4(swaddr(sb + S_YH, n, c), bh[g]);
            ldsm_x4(swaddr(sb + S_YL, n, c), bl[g]);
        }
        #pragma unroll
        for (int mt = 0; mt < 2; ++mt)
            #pragma unroll
            for (int nt = 0; nt < 4; ++nt) {
                const int g = nt >> 1;
                const int p = (nt & 1) * 2;
                mma_tf32(acc[mt][nt], ah[mt], bh[g][p], bh[g][p + 1]);
                mma_tf32(acc[mt][nt], ah[mt], bl[g][p], bl[g][p + 1]);
                mma_tf32(acc[mt][nt], al[mt], bh[g][p], bh[g][p + 1]);
            }
    }

    // ---- epilogue: exp2 + sector-perfect float2 stores ----
    const int gid = lane >> 2;
    const int tig = lane & 3;
    #pragma unroll
    for (int mt = 0; mt < 2; ++mt) {
        const int r0 = rowBase + warpM * 32 + mt * 16 + gid;
        const float sx0 = g_sqx[r0];
        const float sx1 = g_sqx[r0 + 8];
        #pragma unroll
        for (int nt = 0; nt < 4; ++nt) {
            const int col = colBase + warpN * 32 + nt * 8 + 2 * tig;
            const float sy0 = g_sqy[col];
            const float sy1 = g_sqy[col + 1];
            float2 w0, w1;
            w0.x = ex2f(acc[mt][nt][0] - sx0 - sy0);
            w0.y = ex2f(acc[mt][nt][1] - sx0 - sy1);
            w1.x = ex2f(acc[mt][nt][2] - sx1 - sy0);
            w1.y = ex2f(acc[mt][nt][3] - sx1 - sy1);
            *reinterpret_cast<float2*>(out + (size_t)r0 * MROWS + col) = w0;
            *reinterpret_cast<float2*>(out + (size_t)(r0 + 8) * MROWS + col) = w1;
        }
    }
}

extern "C" void kernel_launch(void* const* d_in, const int* in_sizes, int n_in,
                              void* d_out, int out_size) {
    const float* x     = (const float*)d_in[0];
    const float* y     = (const float*)d_in[1];
    const float* gamma = (const float*)d_in[2];
    float* out = (float*)d_out;
    (void)in_sizes; (void)n_in; (void)out_size;

    cudaFuncSetAttribute(rbf_mma_kernel,
                         cudaFuncAttributeMaxDynamicSharedMemorySize, SMEM_TOTAL);

    precompute_kernel<<<2048, 256>>>(x, y, gamma);
    rbf_mma_kernel<<<dim3(MROWS / TILE_N, NROWS / TILE_M), 256, SMEM_TOTAL>>>(
        x, y, gamma, out);
}

// round 8
// speedup vs baseline: 1.6658x; 1.6658x over previous
#include <cuda_runtime.h>
#include <cuda_fp16.h>
#include <cstdint>

// Anisotropic RBF kernel matrix on GB300 via split-fp16 3-pass MMA
// (m16n8k16.f16 + ldmatrix; fp16 mantissa == tf32 mantissa, so the
// h/l split gives the same ~2^-22 product accuracy at 2x the K rate):
//   out[n][m] = exp2( x[n] . (2*log2e*gamma*y[m]) - sqx'[n] - sqy'[m] )
// 3-pass: Ah*Bh + Ah*Bl + Al*Bh, fp32 accumulate.

#define NROWS 8192
#define MROWS 8192
#define DDIM  64
#define TILE_M 128
#define TILE_N 128
#define L2E 1.4426950408889634f

__device__ float g_sqx[NROWS];
__device__ float g_sqy[MROWS];
// precomputed fp16 splits (x plain; y folded with 2*log2e*gamma)
__device__ __half g_xh[NROWS * DDIM];
__device__ __half g_xl[NROWS * DDIM];
__device__ __half g_yh[MROWS * DDIM];
__device__ __half g_yl[MROWS * DDIM];

// ---------------- helpers ----------------
__device__ __forceinline__ uint32_t smem_u32(const void* p) {
    uint32_t a;
    asm("{ .reg .u64 t; cvta.to.shared.u64 t, %1; cvt.u32.u64 %0, t; }"
        : "=r"(a) : "l"(p));
    return a;
}
__device__ __forceinline__ float ex2f(float x) {
    float r;
    asm("ex2.approx.f32 %0, %1;" : "=f"(r) : "f"(x));
    return r;
}
__device__ __forceinline__ void ldsm_x4(uint32_t addr, uint32_t r[4]) {
    asm volatile("ldmatrix.sync.aligned.m8n8.x4.shared.b16 {%0,%1,%2,%3}, [%4];"
                 : "=r"(r[0]), "=r"(r[1]), "=r"(r[2]), "=r"(r[3]) : "r"(addr));
}
__device__ __forceinline__ void mma_f16(float d[4], const uint32_t a[4],
                                        uint32_t b0, uint32_t b1) {
    asm volatile(
        "mma.sync.aligned.m16n8k16.row.col.f32.f16.f16.f32 "
        "{%0,%1,%2,%3}, {%4,%5,%6,%7}, {%8,%9}, {%0,%1,%2,%3};"
        : "+f"(d[0]), "+f"(d[1]), "+f"(d[2]), "+f"(d[3])
        : "r"(a[0]), "r"(a[1]), "r"(a[2]), "r"(a[3]), "r"(b0), "r"(b1));
}

// smem: 4 regions of 16KB (128 rows x 128B): XH XL YH YL
// swizzle: 16B chunk' = chunk ^ (row & 7)
#define R_XH 0
#define R_XL 16384
#define R_YH 32768
#define R_YL 49152
#define SMEM_TOTAL 65536

// ---- precompute: fp16 h/l splits + log2e-scaled squared norms ----
__global__ void precompute_kernel(const float* __restrict__ x,
                                  const float* __restrict__ y,
                                  const float* __restrict__ gamma) {
    int w = (blockIdx.x * blockDim.x + threadIdx.x) >> 5;
    int lane = threadIdx.x & 31;
    float g0 = gamma[lane], g1 = gamma[lane + 32];
    if (w < NROWS) {
        const int row = w;
        float v0 = x[(size_t)row * DDIM + lane];
        float v1 = x[(size_t)row * DDIM + lane + 32];
        float s = g0 * v0 * v0 + g1 * v1 * v1;
        #pragma unroll
        for (int o = 16; o > 0; o >>= 1) s += __shfl_xor_sync(0xffffffffu, s, o);
        if (lane == 0) g_sqx[row] = L2E * s;
        __half h0 = __float2half_rn(v0);
        __half h1 = __float2half_rn(v1);
        g_xh[row * DDIM + lane] = h0;
        g_xh[row * DDIM + lane + 32] = h1;
        g_xl[row * DDIM + lane] = __float2half_rn(v0 - __half2float(h0));
        g_xl[row * DDIM + lane + 32] = __float2half_rn(v1 - __half2float(h1));
    } else {
        const int row = w - NROWS;
        float v0 = y[(size_t)row * DDIM + lane];
        float v1 = y[(size_t)row * DDIM + lane + 32];
        float s = g0 * v0 * v0 + g1 * v1 * v1;
        #pragma unroll
        for (int o = 16; o > 0; o >>= 1) s += __shfl_xor_sync(0xffffffffu, s, o);
        if (lane == 0) g_sqy[row] = L2E * s;
        float b0 = 2.f * L2E * g0 * v0;
        float b1 = 2.f * L2E * g1 * v1;
        __half h0 = __float2half_rn(b0);
        __half h1 = __float2half_rn(b1);
        g_yh[row * DDIM + lane] = h0;
        g_yh[row * DDIM + lane + 32] = h1;
        g_yl[row * DDIM + lane] = __float2half_rn(b0 - __half2float(h0));
        g_yl[row * DDIM + lane + 32] = __float2half_rn(b1 - __half2float(h1));
    }
}

// copy one 16KB region (128 rows x 8 chunks of 16B) global->swizzled smem
__device__ __forceinline__ void copy_region(uint32_t dstbase,
                                            const __half* __restrict__ src,
                                            int tid) {
    const uint4* s = reinterpret_cast<const uint4*>(src);
    #pragma unroll
    for (int j = 0; j < 4; ++j) {
        int idx = j * 256 + tid;          // 0..1023 chunks
        uint4 v = s[idx];
        int row = idx >> 3, c = idx & 7;
        uint32_t a = dstbase + (uint32_t)(row * 128) +
                     (uint32_t)(((c ^ (row & 7)) << 4));
        asm volatile("st.shared.v4.b32 [%0], {%1,%2,%3,%4};"
                     :: "r"(a), "r"(v.x), "r"(v.y), "r"(v.z), "r"(v.w) : "memory");
    }
}

// ---- main kernel: 128x128 tile/CTA, 8 warps (2M x 4N), warp tile 64x32 ----
__global__ __launch_bounds__(256, 2) void rbf_mma_kernel(float* __restrict__ out)
{
    extern __shared__ char smem[];
    const uint32_t sb = smem_u32(smem);
    const int tid = threadIdx.x;
    const int wid = tid >> 5;
    const int lane = tid & 31;
    const int rowBase = blockIdx.y * TILE_M;
    const int colBase = blockIdx.x * TILE_N;

    // ---- load precomputed fp16 tiles into swizzled smem ----
    copy_region(sb + R_XH, g_xh + (size_t)rowBase * DDIM, tid);
    copy_region(sb + R_XL, g_xl + (size_t)rowBase * DDIM, tid);
    copy_region(sb + R_YH, g_yh + (size_t)colBase * DDIM, tid);
    copy_region(sb + R_YL, g_yl + (size_t)colBase * DDIM, tid);
    __syncthreads();

    // ---- mainloop ----
    const int warpM = wid >> 2;   // 0..1 -> rows 64*warpM
    const int warpN = wid & 3;    // 0..3 -> cols 32*warpN

    float acc[4][4][4];
    #pragma unroll
    for (int mt = 0; mt < 4; ++mt)
        #pragma unroll
        for (int nt = 0; nt < 4; ++nt)
            #pragma unroll
            for (int i = 0; i < 4; ++i) acc[mt][nt][i] = 0.f;

    // ldsm lane->address components
    const int arow = warpM * 64 + (lane & 15);              // + mt*16
    const int acb  = lane >> 4;                             // chunk bit
    const int brow = warpN * 32 + (lane & 7) + ((lane >> 4) << 3);  // + g*16
    const int bcb  = (lane >> 3) & 1;

    #pragma unroll
    for (int ks = 0; ks < 4; ++ks) {      // k16 steps
        uint32_t ah[4][4], al[4][4], bh[2][4], bl[2][4];
        #pragma unroll
        for (int mt = 0; mt < 4; ++mt) {
            const int r = arow + mt * 16;
            const int c = 2 * ks + acb;
            const uint32_t a = sb + R_XH + (uint32_t)(r * 128) +
                               (uint32_t)((c ^ (r & 7)) << 4);
            ldsm_x4(a, ah[mt]);
            ldsm_x4(a + 16384, al[mt]);   // XL: identical geometry
        }
        #pragma unroll
        for (int g = 0; g < 2; ++g) {
            const int n = brow + g * 16;
            const int c = 2 * ks + bcb;
            const uint32_t a = sb + R_YH + (uint32_t)(n * 128) +
                               (uint32_t)((c ^ (n & 7)) << 4);
            ldsm_x4(a, bh[g]);
            ldsm_x4(a + 16384, bl[g]);    // YL
        }
        #pragma unroll
        for (int mt = 0; mt < 4; ++mt)
            #pragma unroll
            for (int nt = 0; nt < 4; ++nt) {
                const int g = nt >> 1;
                const int p = (nt & 1) * 2;
                mma_f16(acc[mt][nt], ah[mt], bh[g][p], bh[g][p + 1]);
                mma_f16(acc[mt][nt], ah[mt], bl[g][p], bl[g][p + 1]);
                mma_f16(acc[mt][nt], al[mt], bh[g][p], bh[g][p + 1]);
            }
    }

    // ---- epilogue: exp2 + float2 stores ----
    const int gid = lane >> 2;
    const int tig = lane & 3;
    #pragma unroll
    for (int mt = 0; mt < 4; ++mt) {
        const int r0 = rowBase + warpM * 64 + mt * 16 + gid;
        const float sx0 = g_sqx[r0];
        const float sx1 = g_sqx[r0 + 8];
        #pragma unroll
        for (int nt = 0; nt < 4; ++nt) {
            const int col = colBase + warpN * 32 + nt * 8 + 2 * tig;
            const float sy0 = g_sqy[col];
            const float sy1 = g_sqy[col + 1];
            float2 w0, w1;
            w0.x = ex2f(acc[mt][nt][0] - sx0 - sy0);
            w0.y = ex2f(acc[mt][nt][1] - sx0 - sy1);
            w1.x = ex2f(acc[mt][nt][2] - sx1 - sy0);
            w1.y = ex2f(acc[mt][nt][3] - sx1 - sy1);
            *reinterpret_cast<float2*>(out + (size_t)r0 * MROWS + col) = w0;
            *reinterpret_cast<float2*>(out + (size_t)(r0 + 8) * MROWS + col) = w1;
        }
    }
}

extern "C" void kernel_launch(void* const* d_in, const int* in_sizes, int n_in,
                              void* d_out, int out_size) {
    const float* x     = (const float*)d_in[0];
    const float* y     = (const float*)d_in[1];
    const float* gamma = (const float*)d_in[2];
    float* out = (float*)d_out;
    (void)in_sizes; (void)n_in; (void)out_size;

    cudaFuncSetAttribute(rbf_mma_kernel,
                         cudaFuncAttributeMaxDynamicSharedMemorySize, SMEM_TOTAL);

    precompute_kernel<<<2048, 256>>>(x, y, gamma);
    rbf_mma_kernel<<<dim3(MROWS / TILE_N, NROWS / TILE_M), 256, SMEM_TOTAL>>>(out);
}

// round 12
// speedup vs baseline: 2.2392x; 1.3442x over previous
#include <cuda_runtime.h>
#include <cuda_fp16.h>
#include <cstdint>

// Anisotropic RBF kernel matrix on GB300 via split-fp16 3-pass MMA
// (m16n8k16.f16 + ldmatrix):
//   out[n][m] = exp2( x[n] . (2*log2e*gamma*y[m]) - sqx'[n] - sqy'[m] )
// 3-pass fp32 emulation: Ah*Bh + Ah*Bl + Al*Bh  (fp16 mantissa == tf32).
// R9: cp.async tile fills + smem-bounce epilogue with full-line streaming STG.

#define NROWS 8192
#define MROWS 8192
#define DDIM  64
#define TILE_M 128
#define TILE_N 128
#define L2E 1.4426950408889634f

__device__ float g_sqx[NROWS];
__device__ float g_sqy[MROWS];
// precomputed fp16 splits (x plain; y folded with 2*log2e*gamma); 16B aligned
// for cp.async.
__device__ __align__(16) __half g_xh[NROWS * DDIM];
__device__ __align__(16) __half g_xl[NROWS * DDIM];
__device__ __align__(16) __half g_yh[MROWS * DDIM];
__device__ __align__(16) __half g_yl[MROWS * DDIM];

// ---------------- helpers ----------------
__device__ __forceinline__ uint32_t smem_u32(const void* p) {
    uint32_t a;
    asm("{ .reg .u64 t; cvta.to.shared.u64 t, %1; cvt.u32.u64 %0, t; }"
        : "=r"(a) : "l"(p));
    return a;
}
__device__ __forceinline__ float ex2f(float x) {
    float r;
    asm("ex2.approx.f32 %0, %1;" : "=f"(r) : "f"(x));
    return r;
}
__device__ __forceinline__ void ldsm_x4(uint32_t addr, uint32_t r[4]) {
    asm volatile("ldmatrix.sync.aligned.m8n8.x4.shared.b16 {%0,%1,%2,%3}, [%4];"
                 : "=r"(r[0]), "=r"(r[1]), "=r"(r[2]), "=r"(r[3]) : "r"(addr));
}
__device__ __forceinline__ void mma_f16(float d[4], const uint32_t a[4],
                                        uint32_t b0, uint32_t b1) {
    asm volatile(
        "mma.sync.aligned.m16n8k16.row.col.f32.f16.f16.f32 "
        "{%0,%1,%2,%3}, {%4,%5,%6,%7}, {%8,%9}, {%0,%1,%2,%3};"
        : "+f"(d[0]), "+f"(d[1]), "+f"(d[2]), "+f"(d[3])
        : "r"(a[0]), "r"(a[1]), "r"(a[2]), "r"(a[3]), "r"(b0), "r"(b1));
}

// smem: 4 regions of 16KB (128 rows x 128B), chunk swizzle c' = c ^ (row & 7).
#define R_XH 0
#define R_XL 16384
#define R_YH 32768
#define R_YL 49152
#define SMEM_TOTAL 65536

// epilogue stage: 128 rows x 512B f32, 16B-chunk swizzle on (row & 7)
__device__ __forceinline__ uint32_t stage_addr(uint32_t sb, int r, int c) {
    return sb + (uint32_t)(r * 512) + (uint32_t)((((c >> 2) ^ (r & 7)) << 4) +
                                                 ((c & 3) << 2));
}

// ---- precompute: fp16 h/l splits + log2e-scaled squared norms ----
__global__ void precompute_kernel(const float* __restrict__ x,
                                  const float* __restrict__ y,
                                  const float* __restrict__ gamma) {
    int w = (blockIdx.x * blockDim.x + threadIdx.x) >> 5;
    int lane = threadIdx.x & 31;
    float g0 = gamma[lane], g1 = gamma[lane + 32];
    if (w < NROWS) {
        const int row = w;
        float v0 = x[(size_t)row * DDIM + lane];
        float v1 = x[(size_t)row * DDIM + lane + 32];
        float s = g0 * v0 * v0 + g1 * v1 * v1;
        #pragma unroll
        for (int o = 16; o > 0; o >>= 1) s += __shfl_xor_sync(0xffffffffu, s, o);
        if (lane == 0) g_sqx[row] = L2E * s;
        __half h0 = __float2half_rn(v0);
        __half h1 = __float2half_rn(v1);
        g_xh[row * DDIM + lane] = h0;
        g_xh[row * DDIM + lane + 32] = h1;
        g_xl[row * DDIM + lane] = __float2half_rn(v0 - __half2float(h0));
        g_xl[row * DDIM + lane + 32] = __float2half_rn(v1 - __half2float(h1));
    } else {
        const int row = w - NROWS;
        float v0 = y[(size_t)row * DDIM + lane];
        float v1 = y[(size_t)row * DDIM + lane + 32];
        float s = g0 * v0 * v0 + g1 * v1 * v1;
        #pragma unroll
        for (int o = 16; o > 0; o >>= 1) s += __shfl_xor_sync(0xffffffffu, s, o);
        if (lane == 0) g_sqy[row] = L2E * s;
        float b0 = 2.f * L2E * g0 * v0;
        float b1 = 2.f * L2E * g1 * v1;
        __half h0 = __float2half_rn(b0);
        __half h1 = __float2half_rn(b1);
        g_yh[row * DDIM + lane] = h0;
        g_yh[row * DDIM + lane + 32] = h1;
        g_yl[row * DDIM + lane] = __float2half_rn(b0 - __half2float(h0));
        g_yl[row * DDIM + lane + 32] = __float2half_rn(b1 - __half2float(h1));
    }
}

// async-copy one 16KB region (128 rows x 8 chunks of 16B), global->swizzled smem
__device__ __forceinline__ void copy_region_async(uint32_t dstbase,
                                                  const __half* __restrict__ src,
                                                  int tid) {
    #pragma unroll
    for (int j = 0; j < 4; ++j) {
        int idx = j * 256 + tid;          // 0..1023 chunks
        int row = idx >> 3, c = idx & 7;
        uint32_t a = dstbase + (uint32_t)(row * 128) +
                     (uint32_t)((c ^ (row & 7)) << 4);
        asm volatile("cp.async.cg.shared.global [%0], [%1], 16;"
                     :: "r"(a), "l"(src + (size_t)idx * 8) : "memory");
    }
}

// ---- main kernel: 128x128 tile/CTA, 8 warps (2M x 4N), warp tile 64x32 ----
__global__ __launch_bounds__(256, 2) void rbf_mma_kernel(float* __restrict__ out)
{
    extern __shared__ char smem[];
    const uint32_t sb = smem_u32(smem);
    const int tid = threadIdx.x;
    const int wid = tid >> 5;
    const int lane = tid & 31;
    const int rowBase = blockIdx.y * TILE_M;
    const int colBase = blockIdx.x * TILE_N;

    // ---- async-load precomputed fp16 tiles into swizzled smem ----
    copy_region_async(sb + R_XH, g_xh + (size_t)rowBase * DDIM, tid);
    copy_region_async(sb + R_XL, g_xl + (size_t)rowBase * DDIM, tid);
    copy_region_async(sb + R_YH, g_yh + (size_t)colBase * DDIM, tid);
    copy_region_async(sb + R_YL, g_yl + (size_t)colBase * DDIM, tid);
    asm volatile("cp.async.commit_group;" ::: "memory");
    asm volatile("cp.async.wait_group 0;" ::: "memory");
    __syncthreads();

    // ---- mainloop (validated in R6/R8 — unchanged) ----
    const int warpM = wid >> 2;   // 0..1 -> rows 64*warpM
    const int warpN = wid & 3;    // 0..3 -> cols 32*warpN

    float acc[4][4][4];
    #pragma unroll
    for (int mt = 0; mt < 4; ++mt)
        #pragma unroll
        for (int nt = 0; nt < 4; ++nt)
            #pragma unroll
            for (int i = 0; i < 4; ++i) acc[mt][nt][i] = 0.f;

    const int arow = warpM * 64 + (lane & 15);              // + mt*16
    const int acb  = lane >> 4;                             // chunk bit
    const int brow = warpN * 32 + (lane & 7) + ((lane >> 4) << 3);  // + g*16
    const int bcb  = (lane >> 3) & 1;

    #pragma unroll
    for (int ks = 0; ks < 4; ++ks) {      // k16 steps
        uint32_t ah[4][4], al[4][4], bh[2][4], bl[2][4];
        #pragma unroll
        for (int mt = 0; mt < 4; ++mt) {
            const int r = arow + mt * 16;
            const int c = 2 * ks + acb;
            const uint32_t a = sb + R_XH + (uint32_t)(r * 128) +
                               (uint32_t)((c ^ (r & 7)) << 4);
            ldsm_x4(a, ah[mt]);
            ldsm_x4(a + 16384, al[mt]);   // XL: identical geometry
        }
        #pragma unroll
        for (int g = 0; g < 2; ++g) {
            const int n = brow + g * 16;
            const int c = 2 * ks + bcb;
            const uint32_t a = sb + R_YH + (uint32_t)(n * 128) +
                               (uint32_t)((c ^ (n & 7)) << 4);
            ldsm_x4(a, bh[g]);
            ldsm_x4(a + 16384, bl[g]);    // YL
        }
        #pragma unroll
        for (int mt = 0; mt < 4; ++mt)
            #pragma unroll
            for (int nt = 0; nt < 4; ++nt) {
                const int g = nt >> 1;
                const int p = (nt & 1) * 2;
                mma_f16(acc[mt][nt], ah[mt], bh[g][p], bh[g][p + 1]);
                mma_f16(acc[mt][nt], ah[mt], bl[g][p], bl[g][p + 1]);
                mma_f16(acc[mt][nt], al[mt], bh[g][p], bh[g][p + 1]);
            }
    }

    // all ldsm reads done in every warp before the stage overwrites the tiles
    __syncthreads();

    // ---- epilogue part 1: exp2 + conflict-free STS.64 into the stage ----
    const int gid = lane >> 2;
    const int tig = lane & 3;
    #pragma unroll
    for (int mt = 0; mt < 4; ++mt) {
        const int rA = warpM * 64 + mt * 16 + gid;
        const float sx0 = g_sqx[rowBase + rA];
        const float sx1 = g_sqx[rowBase + rA + 8];
        #pragma unroll
        for (int nt = 0; nt < 4; ++nt) {
            const int cA = warpN * 32 + nt * 8 + 2 * tig;
            const float sy0 = g_sqy[colBase + cA];
            const float sy1 = g_sqy[colBase + cA + 1];
            float w0 = ex2f(acc[mt][nt][0] - sx0 - sy0);
            float w1 = ex2f(acc[mt][nt][1] - sx0 - sy1);
            float w2 = ex2f(acc[mt][nt][2] - sx1 - sy0);
            float w3 = ex2f(acc[mt][nt][3] - sx1 - sy1);
            asm volatile("st.shared.v2.f32 [%0], {%1,%2};"
                         :: "r"(stage_addr(sb, rA, cA)), "f"(w0), "f"(w1)
                         : "memory");
            asm volatile("st.shared.v2.f32 [%0], {%1,%2};"
                         :: "r"(stage_addr(sb, rA + 8, cA)), "f"(w2), "f"(w3)
                         : "memory");
        }
    }
    __syncthreads();

    // ---- epilogue part 2: LDS.128 + full-line streaming STG.128 ----
    // warp w covers rows s*32 + w*4 + (lane>>3); lanes 0-7 cover a 128B span.
    #pragma unroll
    for (int s = 0; s < 4; ++s) {
        const int r = s * 32 + wid * 4 + (lane >> 3);
        float* orow = out + (size_t)(rowBase + r) * MROWS + colBase;
        #pragma unroll
        for (int i = 0; i < 4; ++i) {
            const int c = (lane & 7) * 4 + 32 * i;
            float v0, v1, v2, v3;
            asm volatile("ld.shared.v4.f32 {%0,%1,%2,%3}, [%4];"
                         : "=f"(v0), "=f"(v1), "=f"(v2), "=f"(v3)
                         : "r"(stage_addr(sb, r, c)));
            asm volatile("st.global.cs.v4.f32 [%0], {%1,%2,%3,%4};"
                         :: "l"(orow + c), "f"(v0), "f"(v1), "f"(v2), "f"(v3)
                         : "memory");
        }
    }
}

extern "C" void kernel_launch(void* const* d_in, const int* in_sizes, int n_in,
                              void* d_out, int out_size) {
    const float* x     = (const float*)d_in[0];
    const float* y     = (const float*)d_in[1];
    const float* gamma = (const float*)d_in[2];
    float* out = (float*)d_out;
    (void)in_sizes; (void)n_in; (void)out_size;

    cudaFuncSetAttribute(rbf_mma_kernel,
                         cudaFuncAttributeMaxDynamicSharedMemorySize, SMEM_TOTAL);

    precompute_kernel<<<2048, 256>>>(x, y, gamma);
    rbf_mma_kernel<<<dim3(MROWS / TILE_N, NROWS / TILE_M), 256, SMEM_TOTAL>>>(out);
}

// round 13
// speedup vs baseline: 2.3357x; 1.0431x over previous
#include <cuda_runtime.h>
#include <cuda_fp16.h>
#include <cstdint>

// Anisotropic RBF kernel matrix on GB300 via split-fp16 3-pass MMA:
//   out[n][m] = exp2( x[n] . (2*log2e*gamma*y[m]) - sqx'[n] - sqy'[m] )
// R13: 128x512 strip per CTA, X resident, double-buffered cp.async Y prefetch,
// epilogue staged in the dead Y buffer (two 64-row rounds).

#define NROWS 8192
#define MROWS 8192
#define DDIM  64
#define TILE_M 128
#define TILE_N 128
#define NTILES 4
#define L2E 1.4426950408889634f

__device__ float g_sqx[NROWS];
__device__ float g_sqy[MROWS];
__device__ __align__(16) __half g_xh[NROWS * DDIM];
__device__ __align__(16) __half g_xl[NROWS * DDIM];
__device__ __align__(16) __half g_yh[MROWS * DDIM];
__device__ __align__(16) __half g_yl[MROWS * DDIM];

// ---------------- helpers ----------------
__device__ __forceinline__ uint32_t smem_u32(const void* p) {
    uint32_t a;
    asm("{ .reg .u64 t; cvta.to.shared.u64 t, %1; cvt.u32.u64 %0, t; }"
        : "=r"(a) : "l"(p));
    return a;
}
__device__ __forceinline__ float ex2f(float x) {
    float r;
    asm("ex2.approx.f32 %0, %1;" : "=f"(r) : "f"(x));
    return r;
}
__device__ __forceinline__ void ldsm_x4(uint32_t addr, uint32_t r[4]) {
    asm volatile("ldmatrix.sync.aligned.m8n8.x4.shared.b16 {%0,%1,%2,%3}, [%4];"
                 : "=r"(r[0]), "=r"(r[1]), "=r"(r[2]), "=r"(r[3]) : "r"(addr));
}
__device__ __forceinline__ void mma_f16(float d[4], const uint32_t a[4],
                                        uint32_t b0, uint32_t b1) {
    asm volatile(
        "mma.sync.aligned.m16n8k16.row.col.f32.f16.f16.f32 "
        "{%0,%1,%2,%3}, {%4,%5,%6,%7}, {%8,%9}, {%0,%1,%2,%3};"
        : "+f"(d[0]), "+f"(d[1]), "+f"(d[2]), "+f"(d[3])
        : "r"(a[0]), "r"(a[1]), "r"(a[2]), "r"(a[3]), "r"(b0), "r"(b1));
}

// smem layout: XH 16K | XL 16K | Ybuf0 32K (YH+YL) | Ybuf1 32K
#define O_XH 0
#define O_XL 16384
#define O_YB(b) (32768 + (b) * 32768)
#define SMEM_TOTAL 98304

// epilogue stage (inside dead Y buffer): 64 rows x 512B, 16B-chunk swizzle
__device__ __forceinline__ uint32_t stage_addr(uint32_t base, int r, int c) {
    return base + (uint32_t)(r * 512) + (uint32_t)((((c >> 2) ^ (r & 7)) << 4) +
                                                   ((c & 3) << 2));
}

// ---- precompute: fp16 h/l splits + log2e-scaled squared norms ----
__global__ void precompute_kernel(const float* __restrict__ x,
                                  const float* __restrict__ y,
                                  const float* __restrict__ gamma) {
    int w = (blockIdx.x * blockDim.x + threadIdx.x) >> 5;
    int lane = threadIdx.x & 31;
    float g0 = gamma[lane], g1 = gamma[lane + 32];
    if (w < NROWS) {
        const int row = w;
        float v0 = x[(size_t)row * DDIM + lane];
        float v1 = x[(size_t)row * DDIM + lane + 32];
        float s = g0 * v0 * v0 + g1 * v1 * v1;
        #pragma unroll
        for (int o = 16; o > 0; o >>= 1) s += __shfl_xor_sync(0xffffffffu, s, o);
        if (lane == 0) g_sqx[row] = L2E * s;
        __half h0 = __float2half_rn(v0);
        __half h1 = __float2half_rn(v1);
        g_xh[row * DDIM + lane] = h0;
        g_xh[row * DDIM + lane + 32] = h1;
        g_xl[row * DDIM + lane] = __float2half_rn(v0 - __half2float(h0));
        g_xl[row * DDIM + lane + 32] = __float2half_rn(v1 - __half2float(h1));
    } else {
        const int row = w - NROWS;
        float v0 = y[(size_t)row * DDIM + lane];
        float v1 = y[(size_t)row * DDIM + lane + 32];
        float s = g0 * v0 * v0 + g1 * v1 * v1;
        #pragma unroll
        for (int o = 16; o > 0; o >>= 1) s += __shfl_xor_sync(0xffffffffu, s, o);
        if (lane == 0) g_sqy[row] = L2E * s;
        float b0 = 2.f * L2E * g0 * v0;
        float b1 = 2.f * L2E * g1 * v1;
        __half h0 = __float2half_rn(b0);
        __half h1 = __float2half_rn(b1);
        g_yh[row * DDIM + lane] = h0;
        g_yh[row * DDIM + lane + 32] = h1;
        g_yl[row * DDIM + lane] = __float2half_rn(b0 - __half2float(h0));
        g_yl[row * DDIM + lane + 32] = __float2half_rn(b1 - __half2float(h1));
    }
}

// async-copy one 16KB region (128 rows x 8 chunks of 16B), global->swizzled smem
__device__ __forceinline__ void copy_region_async(uint32_t dstbase,
                                                  const __half* __restrict__ src,
                                                  int tid) {
    #pragma unroll
    for (int j = 0; j < 4; ++j) {
        int idx = j * 256 + tid;
        int row = idx >> 3, c = idx & 7;
        uint32_t a = dstbase + (uint32_t)(row * 128) +
                     (uint32_t)((c ^ (row & 7)) << 4);
        asm volatile("cp.async.cg.shared.global [%0], [%1], 16;"
                     :: "r"(a), "l"(src + (size_t)idx * 8) : "memory");
    }
}

// ---- main kernel: 128x512 strip/CTA, 8 warps (2M x 4N), warp tile 64x32 ----
__global__ __launch_bounds__(256, 2) void rbf_mma_kernel(float* __restrict__ out)
{
    extern __shared__ char smem[];
    const uint32_t sb = smem_u32(smem);
    const int tid = threadIdx.x;
    const int wid = tid >> 5;
    const int lane = tid & 31;
    const int rowBase = blockIdx.y * TILE_M;
    const int colStrip = blockIdx.x * (TILE_N * NTILES);

    // ---- prologue: X + first two Y tiles in flight ----
    copy_region_async(sb + O_XH, g_xh + (size_t)rowBase * DDIM, tid);
    copy_region_async(sb + O_XL, g_xl + (size_t)rowBase * DDIM, tid);
    copy_region_async(sb + O_YB(0), g_yh + (size_t)colStrip * DDIM, tid);
    copy_region_async(sb + O_YB(0) + 16384, g_yl + (size_t)colStrip * DDIM, tid);
    asm volatile("cp.async.commit_group;" ::: "memory");
    copy_region_async(sb + O_YB(1), g_yh + (size_t)(colStrip + TILE_N) * DDIM, tid);
    copy_region_async(sb + O_YB(1) + 16384,
                      g_yl + (size_t)(colStrip + TILE_N) * DDIM, tid);
    asm volatile("cp.async.commit_group;" ::: "memory");

    const int warpM = wid >> 2;   // 0..1
    const int warpN = wid & 3;    // 0..3
    const int arow = warpM * 64 + (lane & 15);
    const int acb  = lane >> 4;
    const int brow = warpN * 32 + (lane & 7) + ((lane >> 4) << 3);
    const int bcb  = (lane >> 3) & 1;
    const int gid = lane >> 2;
    const int tig = lane & 3;

    #pragma unroll
    for (int t = 0; t < NTILES; ++t) {
        const int colBase = colStrip + t * TILE_N;
        const uint32_t yb = sb + O_YB(t & 1);

        if (t == NTILES - 1)
            asm volatile("cp.async.wait_group 0;" ::: "memory");
        else
            asm volatile("cp.async.wait_group 1;" ::: "memory");
        __syncthreads();

        // ---- mainloop (validated R6/R8 geometry) ----
        float acc[4][4][4];
        #pragma unroll
        for (int mt = 0; mt < 4; ++mt)
            #pragma unroll
            for (int nt = 0; nt < 4; ++nt)
                #pragma unroll
                for (int i = 0; i < 4; ++i) acc[mt][nt][i] = 0.f;

        #pragma unroll
        for (int ks = 0; ks < 4; ++ks) {
            uint32_t ah[4][4], al[4][4], bh[2][4], bl[2][4];
            #pragma unroll
            for (int mt = 0; mt < 4; ++mt) {
                const int r = arow + mt * 16;
                const int c = 2 * ks + acb;
                const uint32_t a = sb + O_XH + (uint32_t)(r * 128) +
                                   (uint32_t)((c ^ (r & 7)) << 4);
                ldsm_x4(a, ah[mt]);
                ldsm_x4(a + 16384, al[mt]);
            }
            #pragma unroll
            for (int g = 0; g < 2; ++g) {
                const int n = brow + g * 16;
                const int c = 2 * ks + bcb;
                const uint32_t a = yb + (uint32_t)(n * 128) +
                                   (uint32_t)((c ^ (n & 7)) << 4);
                ldsm_x4(a, bh[g]);
                ldsm_x4(a + 16384, bl[g]);
            }
            #pragma unroll
            for (int mt = 0; mt < 4; ++mt)
                #pragma unroll
                for (int nt = 0; nt < 4; ++nt) {
                    const int g = nt >> 1;
                    const int p = (nt & 1) * 2;
                    mma_f16(acc[mt][nt], ah[mt], bh[g][p], bh[g][p + 1]);
                    mma_f16(acc[mt][nt], ah[mt], bl[g][p], bl[g][p + 1]);
                    mma_f16(acc[mt][nt], al[mt], bh[g][p], bh[g][p + 1]);
                }
        }
        __syncthreads();   // Y(t) dead -> its buffer becomes the stage

        // ---- epilogue: two 64-row rounds staged in yb (32KB) ----
        #pragma unroll
        for (int half = 0; half < 2; ++half) {
            if (warpM == half) {
                #pragma unroll
                for (int mt = 0; mt < 4; ++mt) {
                    const int rl = mt * 16 + gid;          // stage-local row
                    const int rg = rowBase + half * 64 + rl;
                    const float sx0 = g_sqx[rg];
                    const float sx1 = g_sqx[rg + 8];
                    #pragma unroll
                    for (int nt = 0; nt < 4; ++nt) {
                        const int cA = warpN * 32 + nt * 8 + 2 * tig;
                        const float sy0 = g_sqy[colBase + cA];
                        const float sy1 = g_sqy[colBase + cA + 1];
                        float w0 = ex2f(acc[mt][nt][0] - sx0 - sy0);
                        float w1 = ex2f(acc[mt][nt][1] - sx0 - sy1);
                        float w2 = ex2f(acc[mt][nt][2] - sx1 - sy0);
                        float w3 = ex2f(acc[mt][nt][3] - sx1 - sy1);
                        asm volatile("st.shared.v2.f32 [%0], {%1,%2};"
                                     :: "r"(stage_addr(yb, rl, cA)), "f"(w0), "f"(w1)
                                     : "memory");
                        asm volatile("st.shared.v2.f32 [%0], {%1,%2};"
                                     :: "r"(stage_addr(yb, rl + 8, cA)), "f"(w2), "f"(w3)
                                     : "memory");
                    }
                }
            }
            __syncthreads();
            // all 8 warps drain 64 rows: warp-op = 4 rows x full 128B line
            #pragma unroll
            for (int s = 0; s < 2; ++s) {
                const int rl = wid * 8 + s * 4 + (lane >> 3);
                float* orow = out + (size_t)(rowBase + half * 64 + rl) * MROWS + colBase;
                #pragma unroll
                for (int i = 0; i < 4; ++i) {
                    const int c = (lane & 7) * 4 + 32 * i;
                    float v0, v1, v2, v3;
                    asm volatile("ld.shared.v4.f32 {%0,%1,%2,%3}, [%4];"
                                 : "=f"(v0), "=f"(v1), "=f"(v2), "=f"(v3)
                                 : "r"(stage_addr(yb, rl, c)));
                    asm volatile("st.global.cs.v4.f32 [%0], {%1,%2,%3,%4};"
                                 :: "l"(orow + c), "f"(v0), "f"(v1), "f"(v2), "f"(v3)
                                 : "memory");
                }
            }
            __syncthreads();
        }

        // ---- prefetch Y(t+2) into the buffer the stage just freed ----
        if (t + 2 < NTILES) {
            const int pc = colStrip + (t + 2) * TILE_N;
            copy_region_async(yb, g_yh + (size_t)pc * DDIM, tid);
            copy_region_async(yb + 16384, g_yl + (size_t)pc * DDIM, tid);
            asm volatile("cp.async.commit_group;" ::: "memory");
        }
    }
}

extern "C" void kernel_launch(void* const* d_in, const int* in_sizes, int n_in,
                              void* d_out, int out_size) {
    const float* x     = (const float*)d_in[0];
    const float* y     = (const float*)d_in[1];
    const float* gamma = (const float*)d_in[2];
    float* out = (float*)d_out;
    (void)in_sizes; (void)n_in; (void)out_size;

    cudaFuncSetAttribute(rbf_mma_kernel,
                         cudaFuncAttributeMaxDynamicSharedMemorySize, SMEM_TOTAL);

    precompute_kernel<<<2048, 256>>>(x, y, gamma);
    rbf_mma_kernel<<<dim3(MROWS / (TILE_N * NTILES), NROWS / TILE_M),
                     256, SMEM_TOTAL>>>(out);
}

// round 14
// speedup vs baseline: 2.4876x; 1.0650x over previous
#include <cuda_runtime.h>
#include <cuda_fp16.h>
#include <cstdint>

// Anisotropic RBF kernel matrix on GB300 via split-fp16 3-pass MMA:
//   out[n][m] = exp2( x[n] . (2*log2e*gamma*y[m]) - sqx'[n] - sqy'[m] )
// R14: pass-major MMA ordering (acc chain distance 1 -> 16) + per-warp
// private epilogue staged in the dead Y half (3 barriers/tile, warp-autonomous
// MUFU/LSU drain overlapping other warps' HMMAs).

#define NROWS 8192
#define MROWS 8192
#define DDIM  64
#define TILE_M 128
#define TILE_N 128
#define NTILES 4
#define L2E 1.4426950408889634f

__device__ float g_sqx[NROWS];
__device__ float g_sqy[MROWS];
__device__ __align__(16) __half g_xh[NROWS * DDIM];
__device__ __align__(16) __half g_xl[NROWS * DDIM];
__device__ __align__(16) __half g_yh[MROWS * DDIM];
__device__ __align__(16) __half g_yl[MROWS * DDIM];

// ---------------- helpers ----------------
__device__ __forceinline__ uint32_t smem_u32(const void* p) {
    uint32_t a;
    asm("{ .reg .u64 t; cvta.to.shared.u64 t, %1; cvt.u32.u64 %0, t; }"
        : "=r"(a) : "l"(p));
    return a;
}
__device__ __forceinline__ float ex2f(float x) {
    float r;
    asm("ex2.approx.f32 %0, %1;" : "=f"(r) : "f"(x));
    return r;
}
__device__ __forceinline__ void ldsm_x4(uint32_t addr, uint32_t r[4]) {
    asm volatile("ldmatrix.sync.aligned.m8n8.x4.shared.b16 {%0,%1,%2,%3}, [%4];"
                 : "=r"(r[0]), "=r"(r[1]), "=r"(r[2]), "=r"(r[3]) : "r"(addr));
}
__device__ __forceinline__ void mma_f16(float d[4], const uint32_t a[4],
                                        uint32_t b0, uint32_t b1) {
    asm volatile(
        "mma.sync.aligned.m16n8k16.row.col.f32.f16.f16.f32 "
        "{%0,%1,%2,%3}, {%4,%5,%6,%7}, {%8,%9}, {%0,%1,%2,%3};"
        : "+f"(d[0]), "+f"(d[1]), "+f"(d[2]), "+f"(d[3])
        : "r"(a[0]), "r"(a[1]), "r"(a[2]), "r"(a[3]), "r"(b0), "r"(b1));
}

// smem layout: XH 16K | XL 16K | Ybuf0 32K (YH+YL) | Ybuf1 32K
#define O_XH 0
#define O_XL 16384
#define O_YB(b) (32768 + (b) * 32768)
#define SMEM_TOTAL 98304

// per-warp stage: 16 rows x 128B inside the dead Y half; 16B-chunk swizzle
__device__ __forceinline__ uint32_t stage_addr(uint32_t base, int r, int c) {
    return base + (uint32_t)(r * 128) + (uint32_t)((((c >> 2) ^ (r & 7)) << 4) +
                                                   ((c & 3) << 2));
}

// ---- precompute: fp16 h/l splits + log2e-scaled squared norms ----
__global__ void precompute_kernel(const float* __restrict__ x,
                                  const float* __restrict__ y,
                                  const float* __restrict__ gamma) {
    int w = (blockIdx.x * blockDim.x + threadIdx.x) >> 5;
    int lane = threadIdx.x & 31;
    float g0 = gamma[lane], g1 = gamma[lane + 32];
    if (w < NROWS) {
        const int row = w;
        float v0 = x[(size_t)row * DDIM + lane];
        float v1 = x[(size_t)row * DDIM + lane + 32];
        float s = g0 * v0 * v0 + g1 * v1 * v1;
        #pragma unroll
        for (int o = 16; o > 0; o >>= 1) s += __shfl_xor_sync(0xffffffffu, s, o);
        if (lane == 0) g_sqx[row] = L2E * s;
        __half h0 = __float2half_rn(v0);
        __half h1 = __float2half_rn(v1);
        g_xh[row * DDIM + lane] = h0;
        g_xh[row * DDIM + lane + 32] = h1;
        g_xl[row * DDIM + lane] = __float2half_rn(v0 - __half2float(h0));
        g_xl[row * DDIM + lane + 32] = __float2half_rn(v1 - __half2float(h1));
    } else {
        const int row = w - NROWS;
        float v0 = y[(size_t)row * DDIM + lane];
        float v1 = y[(size_t)row * DDIM + lane + 32];
        float s = g0 * v0 * v0 + g1 * v1 * v1;
        #pragma unroll
        for (int o = 16; o > 0; o >>= 1) s += __shfl_xor_sync(0xffffffffu, s, o);
        if (lane == 0) g_sqy[row] = L2E * s;
        float b0 = 2.f * L2E * g0 * v0;
        float b1 = 2.f * L2E * g1 * v1;
        __half h0 = __float2half_rn(b0);
        __half h1 = __float2half_rn(b1);
        g_yh[row * DDIM + lane] = h0;
        g_yh[row * DDIM + lane + 32] = h1;
        g_yl[row * DDIM + lane] = __float2half_rn(b0 - __half2float(h0));
        g_yl[row * DDIM + lane + 32] = __float2half_rn(b1 - __half2float(h1));
    }
}

// async-copy one 16KB region (128 rows x 8 chunks of 16B), global->swizzled smem
__device__ __forceinline__ void copy_region_async(uint32_t dstbase,
                                                  const __half* __restrict__ src,
                                                  int tid) {
    #pragma unroll
    for (int j = 0; j < 4; ++j) {
        int idx = j * 256 + tid;
        int row = idx >> 3, c = idx & 7;
        uint32_t a = dstbase + (uint32_t)(row * 128) +
                     (uint32_t)((c ^ (row & 7)) << 4);
        asm volatile("cp.async.cg.shared.global [%0], [%1], 16;"
                     :: "r"(a), "l"(src + (size_t)idx * 8) : "memory");
    }
}

// ---- main kernel: 128x512 strip/CTA, 8 warps (2M x 4N), warp tile 64x32 ----
__global__ __launch_bounds__(256, 2) void rbf_mma_kernel(float* __restrict__ out)
{
    extern __shared__ char smem[];
    const uint32_t sb = smem_u32(smem);
    const int tid = threadIdx.x;
    const int wid = tid >> 5;
    const int lane = tid & 31;
    const int rowBase = blockIdx.y * TILE_M;
    const int colStrip = blockIdx.x * (TILE_N * NTILES);

    // ---- prologue: X + first two Y tiles in flight ----
    copy_region_async(sb + O_XH, g_xh + (size_t)rowBase * DDIM, tid);
    copy_region_async(sb + O_XL, g_xl + (size_t)rowBase * DDIM, tid);
    copy_region_async(sb + O_YB(0), g_yh + (size_t)colStrip * DDIM, tid);
    copy_region_async(sb + O_YB(0) + 16384, g_yl + (size_t)colStrip * DDIM, tid);
    asm volatile("cp.async.commit_group;" ::: "memory");
    copy_region_async(sb + O_YB(1), g_yh + (size_t)(colStrip + TILE_N) * DDIM, tid);
    copy_region_async(sb + O_YB(1) + 16384,
                      g_yl + (size_t)(colStrip + TILE_N) * DDIM, tid);
    asm volatile("cp.async.commit_group;" ::: "memory");

    const int warpM = wid >> 2;   // 0..1
    const int warpN = wid & 3;    // 0..3
    const int arow = warpM * 64 + (lane & 15);
    const int acb  = lane >> 4;
    const int brow = warpN * 32 + (lane & 7) + ((lane >> 4) << 3);
    const int bcb  = (lane >> 3) & 1;
    const int gid = lane >> 2;
    const int tig = lane & 3;

    #pragma unroll
    for (int t = 0; t < NTILES; ++t) {
        const int colBase = colStrip + t * TILE_N;
        const uint32_t yb = sb + O_YB(t & 1);

        if (t == NTILES - 1)
            asm volatile("cp.async.wait_group 0;" ::: "memory");
        else
            asm volatile("cp.async.wait_group 1;" ::: "memory");
        __syncthreads();

        // ---- mainloop: pass-major MMA (acc reuse distance 16) ----
        float acc[4][4][4];
        #pragma unroll
        for (int mt = 0; mt < 4; ++mt)
            #pragma unroll
            for (int nt = 0; nt < 4; ++nt)
                #pragma unroll
                for (int i = 0; i < 4; ++i) acc[mt][nt][i] = 0.f;

        #pragma unroll
        for (int ks = 0; ks < 4; ++ks) {
            uint32_t ah[4][4], al[4][4], bh[2][4], bl[2][4];
            #pragma unroll
            for (int mt = 0; mt < 4; ++mt) {
                const int r = arow + mt * 16;
                const int c = 2 * ks + acb;
                const uint32_t a = sb + O_XH + (uint32_t)(r * 128) +
                                   (uint32_t)((c ^ (r & 7)) << 4);
                ldsm_x4(a, ah[mt]);
                ldsm_x4(a + 16384, al[mt]);
            }
            #pragma unroll
            for (int g = 0; g < 2; ++g) {
                const int n = brow + g * 16;
                const int c = 2 * ks + bcb;
                const uint32_t a = yb + (uint32_t)(n * 128) +
                                   (uint32_t)((c ^ (n & 7)) << 4);
                ldsm_x4(a, bh[g]);
                ldsm_x4(a + 16384, bl[g]);
            }
            // pass 1: Ah*Bh over all 16 tiles
            #pragma unroll
            for (int mt = 0; mt < 4; ++mt)
                #pragma unroll
                for (int nt = 0; nt < 4; ++nt)
                    mma_f16(acc[mt][nt], ah[mt], bh[nt >> 1][(nt & 1) * 2],
                            bh[nt >> 1][(nt & 1) * 2 + 1]);
            // pass 2: Ah*Bl
            #pragma unroll
            for (int mt = 0; mt < 4; ++mt)
                #pragma unroll
                for (int nt = 0; nt < 4; ++nt)
                    mma_f16(acc[mt][nt], ah[mt], bl[nt >> 1][(nt & 1) * 2],
                            bl[nt >> 1][(nt & 1) * 2 + 1]);
            // pass 3: Al*Bh
            #pragma unroll
            for (int mt = 0; mt < 4; ++mt)
                #pragma unroll
                for (int nt = 0; nt < 4; ++nt)
                    mma_f16(acc[mt][nt], al[mt], bh[nt >> 1][(nt & 1) * 2],
                            bh[nt >> 1][(nt & 1) * 2 + 1]);
        }
        __syncthreads();   // Y(t) fully consumed -> its YL half becomes stages

        // ---- per-warp private epilogue (warp-autonomous, __syncwarp only) ----
        // warp stage: 2KB = 16 rows x 128B at YL + wid*2048
        const uint32_t stg = yb + 16384 + (uint32_t)(wid * 2048);
        #pragma unroll
        for (int mt = 0; mt < 4; ++mt) {
            const int rg = rowBase + warpM * 64 + mt * 16;
            const float sx0 = g_sqx[rg + gid];
            const float sx1 = g_sqx[rg + gid + 8];
            #pragma unroll
            for (int nt = 0; nt < 4; ++nt) {
                const int lc = nt * 8 + 2 * tig;               // warp-local col
                const int gc = colBase + warpN * 32 + lc;
                const float sy0 = g_sqy[gc];
                const float sy1 = g_sqy[gc + 1];
                float w0 = ex2f(acc[mt][nt][0] - sx0 - sy0);
                float w1 = ex2f(acc[mt][nt][1] - sx0 - sy1);
                float w2 = ex2f(acc[mt][nt][2] - sx1 - sy0);
                float w3 = ex2f(acc[mt][nt][3] - sx1 - sy1);
                asm volatile("st.shared.v2.f32 [%0], {%1,%2};"
                             :: "r"(stage_addr(stg, gid, lc)), "f"(w0), "f"(w1)
                             : "memory");
                asm volatile("st.shared.v2.f32 [%0], {%1,%2};"
                             :: "r"(stage_addr(stg, gid + 8, lc)), "f"(w2), "f"(w3)
                             : "memory");
            }
            __syncwarp();
            // drain 16 rows: warp-op = 4 rows x one full 128B line each
            #pragma unroll
            for (int j = 0; j < 4; ++j) {
                const int r = j * 4 + (lane >> 3);
                const int lc4 = (lane & 7) * 4;
                float v0, v1, v2, v3;
                asm volatile("ld.shared.v4.f32 {%0,%1,%2,%3}, [%4];"
                             : "=f"(v0), "=f"(v1), "=f"(v2), "=f"(v3)
                             : "r"(stage_addr(stg, r, lc4)));
                float* dst = out + (size_t)(rg + r) * MROWS +
                             colBase + warpN * 32 + lc4;
                asm volatile("st.global.cs.v4.f32 [%0], {%1,%2,%3,%4};"
                             :: "l"(dst), "f"(v0), "f"(v1), "f"(v2), "f"(v3)
                             : "memory");
            }
            __syncwarp();
        }

        // ---- prefetch Y(t+2) into the buffer the stages just vacated ----
        if (t + 2 < NTILES) {
            __syncthreads();   // all stages drained before overwrite
            const int pc = colStrip + (t + 2) * TILE_N;
            copy_region_async(yb, g_yh + (size_t)pc * DDIM, tid);
            copy_region_async(yb + 16384, g_yl + (size_t)pc * DDIM, tid);
            asm volatile("cp.async.commit_group;" ::: "memory");
        }
    }
}

extern "C" void kernel_launch(void* const* d_in, const int* in_sizes, int n_in,
                              void* d_out, int out_size) {
    const float* x     = (const float*)d_in[0];
    const float* y     = (const float*)d_in[1];
    const float* gamma = (const float*)d_in[2];
    float* out = (float*)d_out;
    (void)in_sizes; (void)n_in; (void)out_size;

    cudaFuncSetAttribute(rbf_mma_kernel,
                         cudaFuncAttributeMaxDynamicSharedMemorySize, SMEM_TOTAL);

    precompute_kernel<<<2048, 256>>>(x, y, gamma);
    rbf_mma_kernel<<<dim3(MROWS / (TILE_N * NTILES), NROWS / TILE_M),
                     256, SMEM_TOTAL>>>(out);
}

// round 16
// speedup vs baseline: 2.5278x; 1.0162x over previous
#include <cuda_runtime.h>
#include <cuda_fp16.h>
#include <cstdint>

// Anisotropic RBF kernel matrix on GB300 via split-fp16 3-pass MMA:
//   out[n][m] = exp2( x[n] . (2*log2e*gamma*y[m]) - sqx'[n] - sqy'[m] )
// R15: NTILES 4 -> 2 (grid 1024 -> 2048 CTAs) to kill wave quantization
// (3.46 -> 6.92 waves: ~13.5% -> ~1% tail loss). Mainloop/epilogue unchanged.

#define NROWS 8192
#define MROWS 8192
#define DDIM  64
#define TILE_M 128
#define TILE_N 128
#define NTILES 2
#define L2E 1.4426950408889634f

__device__ float g_sqx[NROWS];
__device__ float g_sqy[MROWS];
__device__ __align__(16) __half g_xh[NROWS * DDIM];
__device__ __align__(16) __half g_xl[NROWS * DDIM];
__device__ __align__(16) __half g_yh[MROWS * DDIM];
__device__ __align__(16) __half g_yl[MROWS * DDIM];

// ---------------- helpers ----------------
__device__ __forceinline__ uint32_t smem_u32(const void* p) {
    uint32_t a;
    asm("{ .reg .u64 t; cvta.to.shared.u64 t, %1; cvt.u32.u64 %0, t; }"
        : "=r"(a) : "l"(p));
    return a;
}
__device__ __forceinline__ float ex2f(float x) {
    float r;
    asm("ex2.approx.f32 %0, %1;" : "=f"(r) : "f"(x));
    return r;
}
__device__ __forceinline__ void ldsm_x4(uint32_t addr, uint32_t r[4]) {
    asm volatile("ldmatrix.sync.aligned.m8n8.x4.shared.b16 {%0,%1,%2,%3}, [%4];"
                 : "=r"(r[0]), "=r"(r[1]), "=r"(r[2]), "=r"(r[3]) : "r"(addr));
}
__device__ __forceinline__ void mma_f16(float d[4], const uint32_t a[4],
                                        uint32_t b0, uint32_t b1) {
    asm volatile(
        "mma.sync.aligned.m16n8k16.row.col.f32.f16.f16.f32 "
        "{%0,%1,%2,%3}, {%4,%5,%6,%7}, {%8,%9}, {%0,%1,%2,%3};"
        : "+f"(d[0]), "+f"(d[1]), "+f"(d[2]), "+f"(d[3])
        : "r"(a[0]), "r"(a[1]), "r"(a[2]), "r"(a[3]), "r"(b0), "r"(b1));
}

// smem layout: XH 16K | XL 16K | Ybuf0 32K (YH+YL) | Ybuf1 32K
#define O_XH 0
#define O_XL 16384
#define O_YB(b) (32768 + (b) * 32768)
#define SMEM_TOTAL 98304

// per-warp stage: 16 rows x 128B inside the dead Y half; 16B-chunk swizzle
__device__ __forceinline__ uint32_t stage_addr(uint32_t base, int r, int c) {
    return base + (uint32_t)(r * 128) + (uint32_t)((((c >> 2) ^ (r & 7)) << 4) +
                                                   ((c & 3) << 2));
}

// ---- precompute: fp16 h/l splits + log2e-scaled squared norms ----
__global__ void precompute_kernel(const float* __restrict__ x,
                                  const float* __restrict__ y,
                                  const float* __restrict__ gamma) {
    int w = (blockIdx.x * blockDim.x + threadIdx.x) >> 5;
    int lane = threadIdx.x & 31;
    float g0 = gamma[lane], g1 = gamma[lane + 32];
    if (w < NROWS) {
        const int row = w;
        float v0 = x[(size_t)row * DDIM + lane];
        float v1 = x[(size_t)row * DDIM + lane + 32];
        float s = g0 * v0 * v0 + g1 * v1 * v1;
        #pragma unroll
        for (int o = 16; o > 0; o >>= 1) s += __shfl_xor_sync(0xffffffffu, s, o);
        if (lane == 0) g_sqx[row] = L2E * s;
        __half h0 = __float2half_rn(v0);
        __half h1 = __float2half_rn(v1);
        g_xh[row * DDIM + lane] = h0;
        g_xh[row * DDIM + lane + 32] = h1;
        g_xl[row * DDIM + lane] = __float2half_rn(v0 - __half2float(h0));
        g_xl[row * DDIM + lane + 32] = __float2half_rn(v1 - __half2float(h1));
    } else {
        const int row = w - NROWS;
        float v0 = y[(size_t)row * DDIM + lane];
        float v1 = y[(size_t)row * DDIM + lane + 32];
        float s = g0 * v0 * v0 + g1 * v1 * v1;
        #pragma unroll
        for (int o = 16; o > 0; o >>= 1) s += __shfl_xor_sync(0xffffffffu, s, o);
        if (lane == 0) g_sqy[row] = L2E * s;
        float b0 = 2.f * L2E * g0 * v0;
        float b1 = 2.f * L2E * g1 * v1;
        __half h0 = __float2half_rn(b0);
        __half h1 = __float2half_rn(b1);
        g_yh[row * DDIM + lane] = h0;
        g_yh[row * DDIM + lane + 32] = h1;
        g_yl[row * DDIM + lane] = __float2half_rn(b0 - __half2float(h0));
        g_yl[row * DDIM + lane + 32] = __float2half_rn(b1 - __half2float(h1));
    }
}

// async-copy one 16KB region (128 rows x 8 chunks of 16B), global->swizzled smem
__device__ __forceinline__ void copy_region_async(uint32_t dstbase,
                                                  const __half* __restrict__ src,
                                                  int tid) {
    #pragma unroll
    for (int j = 0; j < 4; ++j) {
        int idx = j * 256 + tid;
        int row = idx >> 3, c = idx & 7;
        uint32_t a = dstbase + (uint32_t)(row * 128) +
                     (uint32_t)((c ^ (row & 7)) << 4);
        asm volatile("cp.async.cg.shared.global [%0], [%1], 16;"
                     :: "r"(a), "l"(src + (size_t)idx * 8) : "memory");
    }
}

// ---- main kernel: 128x256 strip/CTA, 8 warps (2M x 4N), warp tile 64x32 ----
__global__ __launch_bounds__(256, 2) void rbf_mma_kernel(float* __restrict__ out)
{
    extern __shared__ char smem[];
    const uint32_t sb = smem_u32(smem);
    const int tid = threadIdx.x;
    const int wid = tid >> 5;
    const int lane = tid & 31;
    const int rowBase = blockIdx.y * TILE_M;
    const int colStrip = blockIdx.x * (TILE_N * NTILES);

    // ---- prologue: X + both Y tiles in flight ----
    copy_region_async(sb + O_XH, g_xh + (size_t)rowBase * DDIM, tid);
    copy_region_async(sb + O_XL, g_xl + (size_t)rowBase * DDIM, tid);
    copy_region_async(sb + O_YB(0), g_yh + (size_t)colStrip * DDIM, tid);
    copy_region_async(sb + O_YB(0) + 16384, g_yl + (size_t)colStrip * DDIM, tid);
    asm volatile("cp.async.commit_group;" ::: "memory");
    copy_region_async(sb + O_YB(1), g_yh + (size_t)(colStrip + TILE_N) * DDIM, tid);
    copy_region_async(sb + O_YB(1) + 16384,
                      g_yl + (size_t)(colStrip + TILE_N) * DDIM, tid);
    asm volatile("cp.async.commit_group;" ::: "memory");

    const int warpM = wid >> 2;   // 0..1
    const int warpN = wid & 3;    // 0..3
    const int arow = warpM * 64 + (lane & 15);
    const int acb  = lane >> 4;
    const int brow = warpN * 32 + (lane & 7) + ((lane >> 4) << 3);
    const int bcb  = (lane >> 3) & 1;
    const int gid = lane >> 2;
    const int tig = lane & 3;

    #pragma unroll
    for (int t = 0; t < NTILES; ++t) {
        const int colBase = colStrip + t * TILE_N;
        const uint32_t yb = sb + O_YB(t);

        if (t == 0)
            asm volatile("cp.async.wait_group 1;" ::: "memory");
        else
            asm volatile("cp.async.wait_group 0;" ::: "memory");
        __syncthreads();

        // ---- mainloop: pass-major MMA (acc reuse distance 16) ----
        float acc[4][4][4];
        #pragma unroll
        for (int mt = 0; mt < 4; ++mt)
            #pragma unroll
            for (int nt = 0; nt < 4; ++nt)
                #pragma unroll
                for (int i = 0; i < 4; ++i) acc[mt][nt][i] = 0.f;

        #pragma unroll
        for (int ks = 0; ks < 4; ++ks) {
            uint32_t ah[4][4], al[4][4], bh[2][4], bl[2][4];
            #pragma unroll
            for (int mt = 0; mt < 4; ++mt) {
                const int r = arow + mt * 16;
                const int c = 2 * ks + acb;
                const uint32_t a = sb + O_XH + (uint32_t)(r * 128) +
                                   (uint32_t)((c ^ (r & 7)) << 4);
                ldsm_x4(a, ah[mt]);
                ldsm_x4(a + 16384, al[mt]);
            }
            #pragma unroll
            for (int g = 0; g < 2; ++g) {
                const int n = brow + g * 16;
                const int c = 2 * ks + bcb;
                const uint32_t a = yb + (uint32_t)(n * 128) +
                                   (uint32_t)((c ^ (n & 7)) << 4);
                ldsm_x4(a, bh[g]);
                ldsm_x4(a + 16384, bl[g]);
            }
            // pass 1: Ah*Bh
            #pragma unroll
            for (int mt = 0; mt < 4; ++mt)
                #pragma unroll
                for (int nt = 0; nt < 4; ++nt)
                    mma_f16(acc[mt][nt], ah[mt], bh[nt >> 1][(nt & 1) * 2],
                            bh[nt >> 1][(nt & 1) * 2 + 1]);
            // pass 2: Ah*Bl
            #pragma unroll
            for (int mt = 0; mt < 4; ++mt)
                #pragma unroll
                for (int nt = 0; nt < 4; ++nt)
                    mma_f16(acc[mt][nt], ah[mt], bl[nt >> 1][(nt & 1) * 2],
                            bl[nt >> 1][(nt & 1) * 2 + 1]);
            // pass 3: Al*Bh
            #pragma unroll
            for (int mt = 0; mt < 4; ++mt)
                #pragma unroll
                for (int nt = 0; nt < 4; ++nt)
                    mma_f16(acc[mt][nt], al[mt], bh[nt >> 1][(nt & 1) * 2],
                            bh[nt >> 1][(nt & 1) * 2 + 1]);
        }
        __syncthreads();   // Y(t) fully consumed -> its YL half becomes stages

        // ---- per-warp private epilogue (warp-autonomous, __syncwarp only) ----
        const uint32_t stg = yb + 16384 + (uint32_t)(wid * 2048);
        #pragma unroll
        for (int mt = 0; mt < 4; ++mt) {
            const int rg = rowBase + warpM * 64 + mt * 16;
            const float sx0 = g_sqx[rg + gid];
            const float sx1 = g_sqx[rg + gid + 8];
            #pragma unroll
            for (int nt = 0; nt < 4; ++nt) {
                const int lc = nt * 8 + 2 * tig;               // warp-local col
                const int gc = colBase + warpN * 32 + lc;
                const float sy0 = g_sqy[gc];
                const float sy1 = g_sqy[gc + 1];
                float w0 = ex2f(acc[mt][nt][0] - sx0 - sy0);
                float w1 = ex2f(acc[mt][nt][1] - sx0 - sy1);
                float w2 = ex2f(acc[mt][nt][2] - sx1 - sy0);
                float w3 = ex2f(acc[mt][nt][3] - sx1 - sy1);
                asm volatile("st.shared.v2.f32 [%0], {%1,%2};"
                             :: "r"(stage_addr(stg, gid, lc)), "f"(w0), "f"(w1)
                             : "memory");
                asm volatile("st.shared.v2.f32 [%0], {%1,%2};"
                             :: "r"(stage_addr(stg, gid + 8, lc)), "f"(w2), "f"(w3)
                             : "memory");
            }
            __syncwarp();
            // drain 16 rows: warp-op = 4 rows x one full 128B line each
            #pragma unroll
            for (int j = 0; j < 4; ++j) {
                const int r = j * 4 + (lane >> 3);
                const int lc4 = (lane & 7) * 4;
                float v0, v1, v2, v3;
                asm volatile("ld.shared.v4.f32 {%0,%1,%2,%3}, [%4];"
                             : "=f"(v0), "=f"(v1), "=f"(v2), "=f"(v3)
                             : "r"(stage_addr(stg, r, lc4)));
                float* dst = out + (size_t)(rg + r) * MROWS +
                             colBase + warpN * 32 + lc4;
                asm volatile("st.global.cs.v4.f32 [%0], {%1,%2,%3,%4};"
                             :: "l"(dst), "f"(v0), "f"(v1), "f"(v2), "f"(v3)
                             : "memory");
            }
            __syncwarp();
        }
    }
}

extern "C" void kernel_launch(void* const* d_in, const int* in_sizes, int n_in,
                              void* d_out, int out_size) {
    const float* x     = (const float*)d_in[0];
    const float* y     = (const float*)d_in[1];
    const float* gamma = (const float*)d_in[2];
    float* out = (float*)d_out;
    (void)in_sizes; (void)n_in; (void)out_size;

    cudaFuncSetAttribute(rbf_mma_kernel,
                         cudaFuncAttributeMaxDynamicSharedMemorySize, SMEM_TOTAL);

    precompute_kernel<<<2048, 256>>>(x, y, gamma);
    rbf_mma_kernel<<<dim3(MROWS / (TILE_N * NTILES), NROWS / TILE_M),
                     256, SMEM_TOTAL>>>(out);
}

// round 17
// speedup vs baseline: 2.6434x; 1.0457x over previous
#include <cuda_runtime.h>
#include <cuda_fp16.h>
#include <cstdint>

// Anisotropic RBF kernel matrix on GB300 via split-fp16 3-pass MMA:
//   out[n][m] = exp2( x[n] . (2*log2e*gamma*y[m]) - sqx'[n] - sqy'[m] )
// R17: barrier-free warp drift — dedicated per-warp epilogue stage (16KB),
// both Y tiles prefetched, ONE __syncthreads total; each warp pipelines
// mainloop->epilogue independently so MUFU/store time hides under tensor.

#define NROWS 8192
#define MROWS 8192
#define DDIM  64
#define TILE_M 128
#define TILE_N 128
#define NTILES 2
#define L2E 1.4426950408889634f

__device__ float g_sqx[NROWS];
__device__ float g_sqy[MROWS];
__device__ __align__(16) __half g_xh[NROWS * DDIM];
__device__ __align__(16) __half g_xl[NROWS * DDIM];
__device__ __align__(16) __half g_yh[MROWS * DDIM];
__device__ __align__(16) __half g_yl[MROWS * DDIM];

// ---------------- helpers ----------------
__device__ __forceinline__ uint32_t smem_u32(const void* p) {
    uint32_t a;
    asm("{ .reg .u64 t; cvta.to.shared.u64 t, %1; cvt.u32.u64 %0, t; }"
        : "=r"(a) : "l"(p));
    return a;
}
__device__ __forceinline__ float ex2f(float x) {
    float r;
    asm("ex2.approx.f32 %0, %1;" : "=f"(r) : "f"(x));
    return r;
}
__device__ __forceinline__ void ldsm_x4(uint32_t addr, uint32_t r[4]) {
    asm volatile("ldmatrix.sync.aligned.m8n8.x4.shared.b16 {%0,%1,%2,%3}, [%4];"
                 : "=r"(r[0]), "=r"(r[1]), "=r"(r[2]), "=r"(r[3]) : "r"(addr));
}
__device__ __forceinline__ void mma_f16(float d[4], const uint32_t a[4],
                                        uint32_t b0, uint32_t b1) {
    asm volatile(
        "mma.sync.aligned.m16n8k16.row.col.f32.f16.f16.f32 "
        "{%0,%1,%2,%3}, {%4,%5,%6,%7}, {%8,%9}, {%0,%1,%2,%3};"
        : "+f"(d[0]), "+f"(d[1]), "+f"(d[2]), "+f"(d[3])
        : "r"(a[0]), "r"(a[1]), "r"(a[2]), "r"(a[3]), "r"(b0), "r"(b1));
}

// smem: XH 16K | XL 16K | Y0 32K | Y1 32K | stage 16K (8 x 2KB per-warp)
#define O_XH 0
#define O_XL 16384
#define O_YB(b) (32768 + (b) * 32768)
#define O_STG 98304
#define SMEM_TOTAL 114688

// per-warp stage slab: 16 rows x 128B; 16B-chunk swizzle
__device__ __forceinline__ uint32_t stage_addr(uint32_t base, int r, int c) {
    return base + (uint32_t)(r * 128) + (uint32_t)((((c >> 2) ^ (r & 7)) << 4) +
                                                   ((c & 3) << 2));
}

// ---- precompute: fp16 h/l splits + log2e-scaled squared norms ----
__global__ void precompute_kernel(const float* __restrict__ x,
                                  const float* __restrict__ y,
                                  const float* __restrict__ gamma) {
    int w = (blockIdx.x * blockDim.x + threadIdx.x) >> 5;
    int lane = threadIdx.x & 31;
    float g0 = gamma[lane], g1 = gamma[lane + 32];
    if (w < NROWS) {
        const int row = w;
        float v0 = x[(size_t)row * DDIM + lane];
        float v1 = x[(size_t)row * DDIM + lane + 32];
        float s = g0 * v0 * v0 + g1 * v1 * v1;
        #pragma unroll
        for (int o = 16; o > 0; o >>= 1) s += __shfl_xor_sync(0xffffffffu, s, o);
        if (lane == 0) g_sqx[row] = L2E * s;
        __half h0 = __float2half_rn(v0);
        __half h1 = __float2half_rn(v1);
        g_xh[row * DDIM + lane] = h0;
        g_xh[row * DDIM + lane + 32] = h1;
        g_xl[row * DDIM + lane] = __float2half_rn(v0 - __half2float(h0));
        g_xl[row * DDIM + lane + 32] = __float2half_rn(v1 - __half2float(h1));
    } else {
        const int row = w - NROWS;
        float v0 = y[(size_t)row * DDIM + lane];
        float v1 = y[(size_t)row * DDIM + lane + 32];
        float s = g0 * v0 * v0 + g1 * v1 * v1;
        #pragma unroll
        for (int o = 16; o > 0; o >>= 1) s += __shfl_xor_sync(0xffffffffu, s, o);
        if (lane == 0) g_sqy[row] = L2E * s;
        float b0 = 2.f * L2E * g0 * v0;
        float b1 = 2.f * L2E * g1 * v1;
        __half h0 = __float2half_rn(b0);
        __half h1 = __float2half_rn(b1);
        g_yh[row * DDIM + lane] = h0;
        g_yh[row * DDIM + lane + 32] = h1;
        g_yl[row * DDIM + lane] = __float2half_rn(b0 - __half2float(h0));
        g_yl[row * DDIM + lane + 32] = __float2half_rn(b1 - __half2float(h1));
    }
}

// async-copy one 16KB region (128 rows x 8 chunks of 16B), global->swizzled smem
__device__ __forceinline__ void copy_region_async(uint32_t dstbase,
                                                  const __half* __restrict__ src,
                                                  int tid) {
    #pragma unroll
    for (int j = 0; j < 4; ++j) {
        int idx = j * 256 + tid;
        int row = idx >> 3, c = idx & 7;
        uint32_t a = dstbase + (uint32_t)(row * 128) +
                     (uint32_t)((c ^ (row & 7)) << 4);
        asm volatile("cp.async.cg.shared.global [%0], [%1], 16;"
                     :: "r"(a), "l"(src + (size_t)idx * 8) : "memory");
    }
}

// ---- main kernel: 128x256 strip/CTA, 8 warps (2M x 4N), warp tile 64x32 ----
__global__ __launch_bounds__(256, 2) void rbf_mma_kernel(float* __restrict__ out)
{
    extern __shared__ char smem[];
    const uint32_t sb = smem_u32(smem);
    const int tid = threadIdx.x;
    const int wid = tid >> 5;
    const int lane = tid & 31;
    const int rowBase = blockIdx.y * TILE_M;
    const int colStrip = blockIdx.x * (TILE_N * NTILES);

    // ---- prologue: X + BOTH Y tiles, one group, one wait, ONE barrier ----
    copy_region_async(sb + O_XH, g_xh + (size_t)rowBase * DDIM, tid);
    copy_region_async(sb + O_XL, g_xl + (size_t)rowBase * DDIM, tid);
    copy_region_async(sb + O_YB(0), g_yh + (size_t)colStrip * DDIM, tid);
    copy_region_async(sb + O_YB(0) + 16384, g_yl + (size_t)colStrip * DDIM, tid);
    copy_region_async(sb + O_YB(1), g_yh + (size_t)(colStrip + TILE_N) * DDIM, tid);
    copy_region_async(sb + O_YB(1) + 16384,
                      g_yl + (size_t)(colStrip + TILE_N) * DDIM, tid);
    asm volatile("cp.async.commit_group;" ::: "memory");
    asm volatile("cp.async.wait_group 0;" ::: "memory");
    __syncthreads();   // the only block-wide barrier in the kernel

    const int warpM = wid >> 2;   // 0..1
    const int warpN = wid & 3;    // 0..3
    const int arow = warpM * 64 + (lane & 15);
    const int acb  = lane >> 4;
    const int brow = warpN * 32 + (lane & 7) + ((lane >> 4) << 3);
    const int bcb  = (lane >> 3) & 1;
    const int gid = lane >> 2;
    const int tig = lane & 3;
    const uint32_t stg = sb + O_STG + (uint32_t)(wid * 2048);  // private slab

    #pragma unroll
    for (int t = 0; t < NTILES; ++t) {
        const int colBase = colStrip + t * TILE_N;
        const uint32_t yb = sb + O_YB(t);

        // ---- mainloop: pass-major MMA (acc reuse distance 16) ----
        float acc[4][4][4];
        #pragma unroll
        for (int mt = 0; mt < 4; ++mt)
            #pragma unroll
            for (int nt = 0; nt < 4; ++nt)
                #pragma unroll
                for (int i = 0; i < 4; ++i) acc[mt][nt][i] = 0.f;

        #pragma unroll
        for (int ks = 0; ks < 4; ++ks) {
            uint32_t ah[4][4], al[4][4], bh[2][4], bl[2][4];
            #pragma unroll
            for (int mt = 0; mt < 4; ++mt) {
                const int r = arow + mt * 16;
                const int c = 2 * ks + acb;
                const uint32_t a = sb + O_XH + (uint32_t)(r * 128) +
                                   (uint32_t)((c ^ (r & 7)) << 4);
                ldsm_x4(a, ah[mt]);
                ldsm_x4(a + 16384, al[mt]);
            }
            #pragma unroll
            for (int g = 0; g < 2; ++g) {
                const int n = brow + g * 16;
                const int c = 2 * ks + bcb;
                const uint32_t a = yb + (uint32_t)(n * 128) +
                                   (uint32_t)((c ^ (n & 7)) << 4);
                ldsm_x4(a, bh[g]);
                ldsm_x4(a + 16384, bl[g]);
            }
            // pass 1: Ah*Bh
            #pragma unroll
            for (int mt = 0; mt < 4; ++mt)
                #pragma unroll
                for (int nt = 0; nt < 4; ++nt)
                    mma_f16(acc[mt][nt], ah[mt], bh[nt >> 1][(nt & 1) * 2],
                            bh[nt >> 1][(nt & 1) * 2 + 1]);
            // pass 2: Ah*Bl
            #pragma unroll
            for (int mt = 0; mt < 4; ++mt)
                #pragma unroll
                for (int nt = 0; nt < 4; ++nt)
                    mma_f16(acc[mt][nt], ah[mt], bl[nt >> 1][(nt & 1) * 2],
                            bl[nt >> 1][(nt & 1) * 2 + 1]);
            // pass 3: Al*Bh
            #pragma unroll
            for (int mt = 0; mt < 4; ++mt)
                #pragma unroll
                for (int nt = 0; nt < 4; ++nt)
                    mma_f16(acc[mt][nt], al[mt], bh[nt >> 1][(nt & 1) * 2],
                            bh[nt >> 1][(nt & 1) * 2 + 1]);
        }

        // ---- per-warp epilogue: fully warp-autonomous (no block barriers) ----
        #pragma unroll
        for (int mt = 0; mt < 4; ++mt) {
            const int rg = rowBase + warpM * 64 + mt * 16;
            const float sx0 = g_sqx[rg + gid];
            const float sx1 = g_sqx[rg + gid + 8];
            #pragma unroll
            for (int nt = 0; nt < 4; ++nt) {
                const int lc = nt * 8 + 2 * tig;               // warp-local col
                const int gc = colBase + warpN * 32 + lc;
                const float sy0 = g_sqy[gc];
                const float sy1 = g_sqy[gc + 1];
                float w0 = ex2f(acc[mt][nt][0] - sx0 - sy0);
                float w1 = ex2f(acc[mt][nt][1] - sx0 - sy1);
                float w2 = ex2f(acc[mt][nt][2] - sx1 - sy0);
                float w3 = ex2f(acc[mt][nt][3] - sx1 - sy1);
                asm volatile("st.shared.v2.f32 [%0], {%1,%2};"
                             :: "r"(stage_addr(stg, gid, lc)), "f"(w0), "f"(w1)
                             : "memory");
                asm volatile("st.shared.v2.f32 [%0], {%1,%2};"
                             :: "r"(stage_addr(stg, gid + 8, lc)), "f"(w2), "f"(w3)
                             : "memory");
            }
            __syncwarp();
            // drain 16 rows: warp-op = 4 rows x one full 128B line each
            #pragma unroll
            for (int j = 0; j < 4; ++j) {
                const int r = j * 4 + (lane >> 3);
                const int lc4 = (lane & 7) * 4;
                float v0, v1, v2, v3;
                asm volatile("ld.shared.v4.f32 {%0,%1,%2,%3}, [%4];"
                             : "=f"(v0), "=f"(v1), "=f"(v2), "=f"(v3)
                             : "r"(stage_addr(stg, r, lc4)));
                float* dst = out + (size_t)(rg + r) * MROWS +
                             colBase + warpN * 32 + lc4;
                asm volatile("st.global.cs.v4.f32 [%0], {%1,%2,%3,%4};"
                             :: "l"(dst), "f"(v0), "f"(v1), "f"(v2), "f"(v3)
                             : "memory");
            }
            __syncwarp();   // slab reused by next mt round
        }
    }
}

extern "C" void kernel_launch(void* const* d_in, const int* in_sizes, int n_in,
                              void* d_out, int out_size) {
    const float* x     = (const float*)d_in[0];
    const float* y     = (const float*)d_in[1];
    const float* gamma = (const float*)d_in[2];
    float* out = (float*)d_out;
    (void)in_sizes; (void)n_in; (void)out_size;

    cudaFuncSetAttribute(rbf_mma_kernel,
                         cudaFuncAttributeMaxDynamicSharedMemorySize, SMEM_TOTAL);

    precompute_kernel<<<2048, 256>>>(x, y, gamma);
    rbf_mma_kernel<<<dim3(MROWS / (TILE_N * NTILES), NROWS / TILE_M),
                     256, SMEM_TOTAL>>>(out);
}